// round 1
// baseline (speedup 1.0000x reference)
#include <cuda_runtime.h>
#include <math.h>

#define CDIM 128
#define BDIM 8
#define NDIM 2048

#define BM 128
#define BN 128
#define BK 16
#define TM 8
#define TN 8

// Scratch (no allocations allowed in kernel_launch)
__device__ float g_g[BDIM * NDIM * CDIM];  // g[b,j,c] = w[b,j]*h[b,j,c]
__device__ float g_w[BDIM * NDIM];         // w[b,j] = exp(h[b,j].v + s0)
__device__ float g_v[CDIM];                // v[c] = sum_d W_w[d,c]*a_w[C+d]
__device__ float g_s0;                     // s0  = sum_d W_b[d]*a_w[C+d]

// ---------------------------------------------------------------------------
// Kernel 0: fold the linear layer + second half of the concat-attention vector
// into a single C-vector v and scalar s0.  One block of 128 threads.
// ---------------------------------------------------------------------------
__global__ void prep_v_kernel(const float* __restrict__ Ww,
                              const float* __restrict__ Wb,
                              const float* __restrict__ aw) {
    int c = threadIdx.x;
    float s = 0.f;
#pragma unroll 8
    for (int d = 0; d < CDIM; d++) s += Ww[d * CDIM + c] * aw[CDIM + d];
    g_v[c] = s;
    if (c == 0) {
        float t = 0.f;
        for (int d = 0; d < CDIM; d++) t += Wb[d] * aw[CDIM + d];
        g_s0 = t;
    }
}

// ---------------------------------------------------------------------------
// Kernel 1: per row (b,j): sj = h.v + s0 ; w = exp(sj) ; g = w*h.
// One 128-thread block per row, 16384 blocks.  ~16 MB traffic, trivial cost.
// ---------------------------------------------------------------------------
__global__ void prep_g_kernel(const float* __restrict__ h) {
    int row = blockIdx.x;        // 0 .. B*N-1
    int c   = threadIdx.x;       // 0 .. 127
    float hv = h[row * CDIM + c];
    float p  = hv * g_v[c];

    __shared__ float red[4];
#pragma unroll
    for (int o = 16; o > 0; o >>= 1) p += __shfl_down_sync(0xffffffffu, p, o);
    if ((c & 31) == 0) red[c >> 5] = p;
    __syncthreads();
    float sj = red[0] + red[1] + red[2] + red[3];
    float w  = expf(sj + g_s0);
    g_g[row * CDIM + c] = w * hv;
    if (c == 0) g_w[row] = w;
}

// ---------------------------------------------------------------------------
// Kernel 2: batched GEMM  Num[b,i,c] = sum_j A[b,i,j] * g[b,j,c]
//           with fused   Den[b,i]   = sum_j A[b,i,j] * w[b,j]
//           out = Num / Den.
// BM=128 x BN=128(=C) x BK=16, 256 threads, 8x8 per-thread microtile.
// Grid: 16 m-tiles x 8 batches = 128 blocks.
// ---------------------------------------------------------------------------
__global__ void __launch_bounds__(256, 1)
attn_gemm_kernel(const float* __restrict__ A, float* __restrict__ out) {
    __shared__ float As[BK][BM + 8];   // transposed A tile, padded vs bank conflicts
    __shared__ float Bs[BK][BN];       // g tile
    __shared__ float ws[BK];           // w tile
    __shared__ float denS[BM];

    const int b  = blockIdx.y;
    const int m0 = blockIdx.x * BM;

    const float* __restrict__ Ab = A   + (size_t)b * NDIM * NDIM;
    const float* __restrict__ gb = g_g + (size_t)b * NDIM * CDIM;
    const float* __restrict__ wb = g_w + (size_t)b * NDIM;

    const int tid = threadIdx.x;
    const int tx  = tid & 15;          // 0..15 (col group)
    const int ty  = tid >> 4;          // 0..15 (row group)
    const int tm0 = ty * TM;
    const int tn0 = tx * TN;

    float acc[TM][TN];
#pragma unroll
    for (int i = 0; i < TM; i++)
#pragma unroll
        for (int j = 0; j < TN; j++) acc[i][j] = 0.f;
    float den[TM];
#pragma unroll
    for (int i = 0; i < TM; i++) den[i] = 0.f;

    for (int k0 = 0; k0 < NDIM; k0 += BK) {
        // --- load A tile [BM x BK] -> As[k][m] (transposed). 512 float4, 2/thread.
#pragma unroll
        for (int l = 0; l < 2; l++) {
            int f  = tid * 2 + l;          // 0..511
            int r  = f >> 2;               // row in tile (0..127)
            int kq = (f & 3) * 4;          // k offset (0,4,8,12)
            float4 v = *(const float4*)&Ab[(size_t)(m0 + r) * NDIM + k0 + kq];
            As[kq + 0][r] = v.x;
            As[kq + 1][r] = v.y;
            As[kq + 2][r] = v.z;
            As[kq + 3][r] = v.w;
        }
        // --- load g tile [BK x BN]. 512 float4, 2/thread, direct layout.
#pragma unroll
        for (int l = 0; l < 2; l++) {
            int f  = tid * 2 + l;
            int r  = f >> 5;               // k row (0..15)
            int cq = (f & 31) * 4;         // col (0..124 step 4)
            *(float4*)&Bs[r][cq] = *(const float4*)&gb[(k0 + r) * CDIM + cq];
        }
        if (tid < BK) ws[tid] = wb[k0 + tid];
        __syncthreads();

#pragma unroll
        for (int k = 0; k < BK; k++) {
            float ra[TM], rb[TN];
#pragma unroll
            for (int i = 0; i < TM; i++) ra[i] = As[k][tm0 + i];
#pragma unroll
            for (int j = 0; j < TN; j++) rb[j] = Bs[k][tn0 + j];
#pragma unroll
            for (int i = 0; i < TM; i++)
#pragma unroll
                for (int j = 0; j < TN; j++)
                    acc[i][j] = fmaf(ra[i], rb[j], acc[i][j]);
            if (tx == 0) {
                float wk = ws[k];
#pragma unroll
                for (int i = 0; i < TM; i++) den[i] = fmaf(ra[i], wk, den[i]);
            }
        }
        __syncthreads();
    }

    if (tx == 0) {
#pragma unroll
        for (int i = 0; i < TM; i++) denS[tm0 + i] = den[i];
    }
    __syncthreads();

    float* __restrict__ ob = out + ((size_t)b * NDIM + m0) * CDIM;
#pragma unroll
    for (int i = 0; i < TM; i++) {
        float inv = 1.0f / denS[tm0 + i];
        float4 v0, v1;
        v0.x = acc[i][0] * inv; v0.y = acc[i][1] * inv;
        v0.z = acc[i][2] * inv; v0.w = acc[i][3] * inv;
        v1.x = acc[i][4] * inv; v1.y = acc[i][5] * inv;
        v1.z = acc[i][6] * inv; v1.w = acc[i][7] * inv;
        *(float4*)&ob[(tm0 + i) * CDIM + tn0]     = v0;
        *(float4*)&ob[(tm0 + i) * CDIM + tn0 + 4] = v1;
    }
}

// ---------------------------------------------------------------------------
// Launch.  Inputs (metadata order): h, A, W_w, W_b, a_w, a_b.
// a_b and a_w[:C] cancel in the softmax ratio and are never read.
// ---------------------------------------------------------------------------
extern "C" void kernel_launch(void* const* d_in, const int* in_sizes, int n_in,
                              void* d_out, int out_size) {
    (void)in_sizes; (void)n_in; (void)out_size;
    const float* h  = (const float*)d_in[0];
    const float* A  = (const float*)d_in[1];
    const float* Ww = (const float*)d_in[2];
    const float* Wb = (const float*)d_in[3];
    const float* aw = (const float*)d_in[4];
    float* out = (float*)d_out;

    prep_v_kernel<<<1, CDIM>>>(Ww, Wb, aw);
    prep_g_kernel<<<BDIM * NDIM, CDIM>>>(h);
    dim3 grid(NDIM / BM, BDIM);
    attn_gemm_kernel<<<grid, 256>>>(A, out);
}

// round 4
// speedup vs baseline: 5.0936x; 5.0936x over previous
#include <cuda_runtime.h>
#include <math.h>
#include <cstdint>

#define CDIM 128
#define BDIM 8
#define NDIM 2048
#define GROWS 129            // 128 channel rows + 1 w row

// GEMM tiling
#define NSTAGE 3
#define A_ST   (128 * 36)    // floats per A stage (rows x padded 36)
#define B_ST   (130 * 36)    // floats per B stage (129 rows used, 1 pad row)
#define B_OFF  (NSTAGE * A_ST)               // float offset of B stages
#define DENS_OFF (NSTAGE * (A_ST + B_ST))    // float offset of denS[128]
#define SMEM_FLOATS (DENS_OFF + 128)
#define SMEM_TOTAL (SMEM_FLOATS * 4)         // 111,968 bytes

// ---------------- device scratch ----------------
__device__ float g_gT[BDIM * GROWS * NDIM];  // [b][row][j]; row<128: tf32(w*h), row 128: tf32(w)
__device__ float g_v[CDIM];
__device__ float g_s0;

// ---------------- helpers ----------------
__device__ __forceinline__ uint32_t smem_u32(const void* p) {
    uint32_t a;
    asm("{ .reg .u64 t; cvta.to.shared.u64 t, %1; cvt.u32.u64 %0, t; }" : "=r"(a) : "l"(p));
    return a;
}
__device__ __forceinline__ uint32_t tf32u(float x) {
    uint32_t u;
    asm("cvt.rna.tf32.f32 %0, %1;" : "=r"(u) : "f"(x));
    return u;
}
__device__ __forceinline__ void cp16(uint32_t dst, const float* src) {
    asm volatile("cp.async.cg.shared.global [%0], [%1], 16;" :: "r"(dst), "l"(src));
}
#define CP_COMMIT() asm volatile("cp.async.commit_group;" ::: "memory")
#define CP_WAIT(n)  asm volatile("cp.async.wait_group %0;" :: "n"(n) : "memory")

#define MMA_TF32(d, a0, a1, a2, a3, b0, b1) \
    asm volatile("mma.sync.aligned.m16n8k8.row.col.f32.tf32.tf32.f32 " \
        "{%0,%1,%2,%3}, {%4,%5,%6,%7}, {%8,%9}, {%0,%1,%2,%3};" \
        : "+f"((d)[0]), "+f"((d)[1]), "+f"((d)[2]), "+f"((d)[3]) \
        : "r"(a0), "r"(a1), "r"(a2), "r"(a3), "r"(b0), "r"(b1))

// ---------------------------------------------------------------------------
// prep_v: blocks 0..127 -> v[c] = sum_d Ww[d,c]*aw[C+d];  block 128 -> s0.
// ---------------------------------------------------------------------------
__global__ void prep_v_kernel(const float* __restrict__ Ww,
                              const float* __restrict__ Wb,
                              const float* __restrict__ aw) {
    int c = blockIdx.x;
    int d = threadIdx.x;
    float x = (c < CDIM) ? Ww[d * CDIM + c] * aw[CDIM + d] : Wb[d] * aw[CDIM + d];
    __shared__ float red[4];
#pragma unroll
    for (int o = 16; o > 0; o >>= 1) x += __shfl_down_sync(0xffffffffu, x, o);
    if ((d & 31) == 0) red[d >> 5] = x;
    __syncthreads();
    if (d == 0) {
        float t = red[0] + red[1] + red[2] + red[3];
        if (c < CDIM) g_v[c] = t; else g_s0 = t;
    }
}

// ---------------------------------------------------------------------------
// prep_g: per 32-token tile: w = exp(h.v + s0); write gT rows (tf32-rounded):
// row c (<128): w*h[., c];  row 128: w.
// ---------------------------------------------------------------------------
__global__ void __launch_bounds__(256)
prep_g_kernel(const float* __restrict__ h) {
    __shared__ float hs[32 * 129];
    __shared__ float vsh[CDIM];
    __shared__ float wsh[32];

    const int b  = blockIdx.y;
    const int j0 = blockIdx.x * 32;
    const int tid = threadIdx.x;
    const int wid = tid >> 5, lid = tid & 31;

    if (tid < CDIM) vsh[tid] = g_v[tid];
    const float* hb = h + ((size_t)b * NDIM + j0) * CDIM;
#pragma unroll
    for (int idx = tid; idx < 32 * CDIM; idx += 256) {
        int r = idx >> 7, c = idx & 127;
        hs[r * 129 + c] = hb[r * CDIM + c];
    }
    __syncthreads();

    float s0 = g_s0;
#pragma unroll
    for (int rr = 0; rr < 4; rr++) {
        int r = wid * 4 + rr;
        float p = 0.f;
#pragma unroll
        for (int q = 0; q < 4; q++)
            p += hs[r * 129 + lid + 32 * q] * vsh[lid + 32 * q];
#pragma unroll
        for (int o = 16; o > 0; o >>= 1) p += __shfl_down_sync(0xffffffffu, p, o);
        if (lid == 0) wsh[r] = expf(p + s0);
    }
    __syncthreads();

    float* Gb = g_gT + (size_t)b * GROWS * NDIM;
#pragma unroll
    for (int idx = tid; idx < CDIM * 32; idx += 256) {
        int c = idx >> 5, jr = idx & 31;
        Gb[(size_t)c * NDIM + j0 + jr] =
            __uint_as_float(tf32u(wsh[jr] * hs[jr * 129 + c]));
    }
    if (tid < 32)
        Gb[(size_t)CDIM * NDIM + j0 + tid] = __uint_as_float(tf32u(wsh[tid]));
}

// ---------------------------------------------------------------------------
// Main GEMM: Num[128 x 128] = Atile . G^T via mma.sync tf32, Den fused scalar.
// 4 warps (2x2), warp tile m64 x n64, BK=32 per stage, 3-stage cp.async.
// ---------------------------------------------------------------------------
__device__ __forceinline__ void load_stage(uint32_t sb, int s, int it, int tid,
                                           const float* __restrict__ Ab,
                                           const float* __restrict__ Gb) {
    const int k0 = it * 32;
    const uint32_t abase = sb + s * (A_ST * 4);
    const uint32_t bbase = sb + (B_OFF + s * B_ST) * 4;
    const float* As = Ab + k0;
    const float* Bs = Gb + k0;
#pragma unroll
    for (int l = 0; l < 8; l++) {              // A: 1024 16B chunks
        int idx = tid + l * 128;
        int r = idx >> 3, c = idx & 7;
        cp16(abase + (r * 36 + c * 4) * 4, As + (size_t)r * NDIM + c * 4);
    }
#pragma unroll
    for (int l = 0; l < 9; l++) {              // B: 1032 16B chunks (129 rows)
        int idx = tid + l * 128;
        if (idx < GROWS * 8) {
            int r = idx >> 3, c = idx & 7;
            cp16(bbase + (r * 36 + c * 4) * 4, Bs + (size_t)r * NDIM + c * 4);
        }
    }
}

__global__ void __launch_bounds__(128, 1)
attn_mma_kernel(const float* __restrict__ A, float* __restrict__ out) {
    extern __shared__ __align__(16) float smf[];
    const uint32_t sb = smem_u32(smf);
    const int tid = threadIdx.x;
    const int lane = tid & 31;
    const int g = lane >> 2, t = lane & 3;
    const int wm = (tid >> 5) >> 1, wn = (tid >> 5) & 1;
    const int b = blockIdx.y, m0 = blockIdx.x * 128;

    const float* __restrict__ Ab = A + (size_t)b * NDIM * NDIM + (size_t)m0 * NDIM;
    const float* __restrict__ Gb = g_gT + (size_t)b * GROWS * NDIM;

    float acc[4][8][4];
#pragma unroll
    for (int mf = 0; mf < 4; mf++)
#pragma unroll
        for (int ch = 0; ch < 8; ch++)
#pragma unroll
            for (int q = 0; q < 4; q++) acc[mf][ch][q] = 0.f;
    float den[8];
#pragma unroll
    for (int i = 0; i < 8; i++) den[i] = 0.f;

    load_stage(sb, 0, 0, tid, Ab, Gb); CP_COMMIT();
    load_stage(sb, 1, 1, tid, Ab, Gb); CP_COMMIT();

    for (int it = 0; it < NDIM / 32; ++it) {
        const int s = it % NSTAGE;
        CP_WAIT(1);
        __syncthreads();
        const int nx = it + 2;
        if (nx < NDIM / 32) load_stage(sb, nx % NSTAGE, nx, tid, Ab, Gb);
        CP_COMMIT();

        const float* Asf = smf + s * A_ST;
        const float* Bsf = smf + B_OFF + s * B_ST;
#pragma unroll
        for (int kk = 0; kk < 4; kk++) {
            const int kb = kk * 8 + t;
            uint32_t bf0[8], bf1[8];
#pragma unroll
            for (int ch = 0; ch < 8; ch++) {
                const int n = wn * 64 + ch * 8 + g;
                bf0[ch] = __float_as_uint(Bsf[n * 36 + kb]);
                bf1[ch] = __float_as_uint(Bsf[n * 36 + kb + 4]);
            }
            float wv0 = 0.f, wv1 = 0.f;
            if (wn == 0) {
                wv0 = Bsf[128 * 36 + kb];
                wv1 = Bsf[128 * 36 + kb + 4];
            }
#pragma unroll
            for (int mf = 0; mf < 4; mf++) {
                const int r = wm * 64 + mf * 16 + g;
                uint32_t a0 = tf32u(Asf[r * 36 + kb]);
                uint32_t a1 = tf32u(Asf[(r + 8) * 36 + kb]);
                uint32_t a2 = tf32u(Asf[r * 36 + kb + 4]);
                uint32_t a3 = tf32u(Asf[(r + 8) * 36 + kb + 4]);
                if (wn == 0) {
                    den[2 * mf]     = fmaf(__uint_as_float(a0), wv0,
                                      fmaf(__uint_as_float(a2), wv1, den[2 * mf]));
                    den[2 * mf + 1] = fmaf(__uint_as_float(a1), wv0,
                                      fmaf(__uint_as_float(a3), wv1, den[2 * mf + 1]));
                }
#pragma unroll
                for (int ch = 0; ch < 8; ch++)
                    MMA_TF32(acc[mf][ch], a0, a1, a2, a3, bf0[ch], bf1[ch]);
            }
        }
    }

    CP_WAIT(0);
    __syncthreads();

    // ---- denominator: quad-reduce over t, publish to smem ----
    float* denS = smf + DENS_OFF;
    if (wn == 0) {
#pragma unroll
        for (int i = 0; i < 8; i++) {
            den[i] += __shfl_xor_sync(0xffffffffu, den[i], 1);
            den[i] += __shfl_xor_sync(0xffffffffu, den[i], 2);
        }
        if (t == 0) {
#pragma unroll
            for (int mf = 0; mf < 4; mf++) {
                denS[wm * 64 + mf * 16 + g]     = den[2 * mf];
                denS[wm * 64 + mf * 16 + g + 8] = den[2 * mf + 1];
            }
        }
    }
    __syncthreads();

    // ---- scale + stage to smem (stg[128][132]) ----
    float* stg = smf;
#pragma unroll
    for (int mf = 0; mf < 4; mf++) {
        const int r0 = wm * 64 + mf * 16 + g;
        const int r1 = r0 + 8;
        const float inv0 = 1.0f / denS[r0];
        const float inv1 = 1.0f / denS[r1];
#pragma unroll
        for (int ch = 0; ch < 8; ch++) {
            const int col = wn * 64 + ch * 8 + 2 * t;
            float2 v0 = make_float2(acc[mf][ch][0] * inv0, acc[mf][ch][1] * inv0);
            float2 v1 = make_float2(acc[mf][ch][2] * inv1, acc[mf][ch][3] * inv1);
            *(float2*)&stg[r0 * 132 + col] = v0;
            *(float2*)&stg[r1 * 132 + col] = v1;
        }
    }
    __syncthreads();

    float* __restrict__ ob = out + ((size_t)b * NDIM + m0) * CDIM;
#pragma unroll 4
    for (int idx = tid; idx < 128 * 32; idx += 128) {
        int r = idx >> 5, c = idx & 31;
        *(float4*)&ob[r * CDIM + c * 4] = *(const float4*)&stg[r * 132 + c * 4];
    }
}

// ---------------------------------------------------------------------------
extern "C" void kernel_launch(void* const* d_in, const int* in_sizes, int n_in,
                              void* d_out, int out_size) {
    (void)in_sizes; (void)n_in; (void)out_size;
    const float* h  = (const float*)d_in[0];
    const float* A  = (const float*)d_in[1];
    const float* Ww = (const float*)d_in[2];
    const float* Wb = (const float*)d_in[3];
    const float* aw = (const float*)d_in[4];
    float* out = (float*)d_out;

    cudaFuncSetAttribute(attn_mma_kernel,
                         cudaFuncAttributeMaxDynamicSharedMemorySize, SMEM_TOTAL);

    prep_v_kernel<<<CDIM + 1, CDIM>>>(Ww, Wb, aw);
    prep_g_kernel<<<dim3(NDIM / 32, BDIM), 256>>>(h);
    attn_mma_kernel<<<dim3(NDIM / 128, BDIM), 128, SMEM_TOTAL>>>(A, out);
}

// round 7
// speedup vs baseline: 5.9349x; 1.1652x over previous
#include <cuda_runtime.h>
#include <cuda_fp16.h>
#include <math.h>
#include <cstdint>

#define CDIM 128
#define BDIM 8
#define NDIM 2048

// ---------------- GEMM tiling ----------------
#define NSTAGE 4
#define BK 32
#define NITER (NDIM / BK)          // 64
#define A_ROWP 40                  // halves per A row (32 data + 8 pad) -> 80B stride
#define A_STB (128 * A_ROWP * 2)   // 10240 B per A stage
#define B_STB (136 * A_ROWP * 2)   // 10880 B per B stage (128 g + 1 w + 7 zero)
#define B_OFFB (NSTAGE * A_STB)    // 40960
#define DEN_OFFB (B_OFFB + NSTAGE * B_STB)   // 84480
#define SMEM_TOTAL (DEN_OFFB + 128 * 4)      // 84992 B

// ---------------- device scratch ----------------
__device__ __half g_gT[BDIM * CDIM * NDIM];  // [b][c][j] = fp16(w*h)
__device__ __half g_w[BDIM * NDIM];          // [b][j]    = fp16(w)

// ---------------- helpers ----------------
__device__ __forceinline__ uint32_t smem_u32(const void* p) {
    uint32_t a;
    asm("{ .reg .u64 t; cvta.to.shared.u64 t, %1; cvt.u32.u64 %0, t; }" : "=r"(a) : "l"(p));
    return a;
}
__device__ __forceinline__ void cp16(uint32_t dst, const void* src) {
    asm volatile("cp.async.cg.shared.global [%0], [%1], 16;" :: "r"(dst), "l"(src));
}
#define CP_COMMIT() asm volatile("cp.async.commit_group;" ::: "memory")
#define CP_WAIT(n)  asm volatile("cp.async.wait_group %0;" :: "n"(n) : "memory")

#define LDSM_X4(r0, r1, r2, r3, a) \
    asm volatile("ldmatrix.sync.aligned.m8n8.x4.shared.b16 {%0,%1,%2,%3}, [%4];" \
        : "=r"(r0), "=r"(r1), "=r"(r2), "=r"(r3) : "r"(a))
#define LDSM_X2(r0, r1, a) \
    asm volatile("ldmatrix.sync.aligned.m8n8.x2.shared.b16 {%0,%1}, [%2];" \
        : "=r"(r0), "=r"(r1) : "r"(a))

#define MMA_F16(d, a0, a1, a2, a3, b0, b1) \
    asm volatile("mma.sync.aligned.m16n8k16.row.col.f32.f16.f16.f32 " \
        "{%0,%1,%2,%3}, {%4,%5,%6,%7}, {%8,%9}, {%0,%1,%2,%3};" \
        : "+f"((d)[0]), "+f"((d)[1]), "+f"((d)[2]), "+f"((d)[3]) \
        : "r"(a0), "r"(a1), "r"(a2), "r"(a3), "r"(b0), "r"(b1))

// ---------------------------------------------------------------------------
// prep_g: per 128-token tile (grid 16 x 8, 256 thr):
//   v[c] = sum_d Ww[d,c]*aw[C+d];  s0 = Wb . aw[C:]
//   w[j] = exp(h[j].v + s0)
//   g_gT[b][c][j] = fp16(w[j]*h[j][c]) ;  g_w[b][j] = fp16(w[j])
// ---------------------------------------------------------------------------
__global__ void __launch_bounds__(256)
prep_g_kernel(const float* __restrict__ h,
              const float* __restrict__ Ww,
              const float* __restrict__ Wb,
              const float* __restrict__ aw) {
    extern __shared__ float hs[];          // [128][129] (pad keeps reads conflict-free)
    __shared__ float vsh[CDIM];
    __shared__ float wsh[128];
    __shared__ float s0sh;

    const int b  = blockIdx.y;
    const int j0 = blockIdx.x * 128;
    const int tid = threadIdx.x;
    const int wid = tid >> 5, lid = tid & 31;

    // v (threads 0-127) and s0 (warp 4)
    if (tid < CDIM) {
        float s = 0.f;
#pragma unroll 8
        for (int d = 0; d < CDIM; d++) s += Ww[d * CDIM + tid] * aw[CDIM + d];
        vsh[tid] = s;
    } else if (wid == 4) {
        float x = 0.f;
#pragma unroll
        for (int q = 0; q < 4; q++) {
            int d = lid + 32 * q;
            x += Wb[d] * aw[CDIM + d];
        }
#pragma unroll
        for (int o = 16; o > 0; o >>= 1) x += __shfl_down_sync(0xffffffffu, x, o);
        if (lid == 0) s0sh = x;
    }

    // load h tile: float4 LDG, scalar STS (row stride 129*4B is not 16B-aligned)
    const float* hb = h + ((size_t)b * NDIM + j0) * CDIM;
#pragma unroll
    for (int l = 0; l < 16; l++) {
        int idx = tid + l * 256;           // float4 index, 4096 total
        int r = idx >> 5, c = (idx & 31) * 4;
        float4 v = *(const float4*)&hb[(size_t)r * CDIM + c];
        float* d = &hs[r * 129 + c];
        d[0] = v.x; d[1] = v.y; d[2] = v.z; d[3] = v.w;
    }
    __syncthreads();

    // w per token (each warp: 16 tokens)
    const float s0 = s0sh;
#pragma unroll
    for (int rr = 0; rr < 16; rr++) {
        int r = wid * 16 + rr;
        float p = 0.f;
#pragma unroll
        for (int q = 0; q < 4; q++)
            p += hs[r * 129 + lid + 32 * q] * vsh[lid + 32 * q];
#pragma unroll
        for (int o = 16; o > 0; o >>= 1) p += __shfl_down_sync(0xffffffffu, p, o);
        if (lid == 0) wsh[r] = expf(p + s0);
    }
    __syncthreads();

    // write gT (fp16) coalesced in j
    __half* Gb = g_gT + (size_t)b * CDIM * NDIM;
#pragma unroll
    for (int l = 0; l < 64; l++) {
        int idx = tid + l * 256;           // 16384 total
        int c = idx >> 7, j = idx & 127;
        Gb[(size_t)c * NDIM + j0 + j] = __float2half_rn(wsh[j] * hs[j * 129 + c]);
    }
    if (tid < 128) g_w[(size_t)b * NDIM + j0 + tid] = __float2half_rn(wsh[tid]);
}

// ---------------------------------------------------------------------------
// Main GEMM (fp16 mma.sync): Num[128x128] = A_tile . G^T, Den via w-row MMA.
// 256 thr = 8 warps (wm 0-1, wn 0-3), warp tile m64 x n32, 4-stage pipeline.
// ---------------------------------------------------------------------------
__device__ __forceinline__ void ldgA(const float* __restrict__ Ab, int it, int tid,
                                     float4 (&ra)[4]) {
    const float* src = Ab + it * BK;
#pragma unroll
    for (int l = 0; l < 4; l++) {
        int idx = tid + l * 256;           // 1024 float4 per stage
        int r = idx >> 3, c = (idx & 7) * 4;
        ra[l] = *(const float4*)&src[(size_t)r * NDIM + c];
    }
}
__device__ __forceinline__ void stsA(uint32_t sb, int s, int tid, const float4 (&ra)[4]) {
    const uint32_t base = sb + s * A_STB;
#pragma unroll
    for (int l = 0; l < 4; l++) {
        int idx = tid + l * 256;
        int r = idx >> 3, c = (idx & 7) * 4;
        __half2 h0 = __floats2half2_rn(ra[l].x, ra[l].y);
        __half2 h1 = __floats2half2_rn(ra[l].z, ra[l].w);
        asm volatile("st.shared.v2.b32 [%0], {%1,%2};"
                     :: "r"(base + (r * A_ROWP + c) * 2),
                        "r"(*(uint32_t*)&h0), "r"(*(uint32_t*)&h1) : "memory");
    }
}
__device__ __forceinline__ void cpB(uint32_t sb, int s, int it, int tid,
                                    const __half* __restrict__ Gb,
                                    const __half* __restrict__ wb) {
    const int k0 = it * BK;
    const uint32_t base = sb + B_OFFB + s * B_STB;
#pragma unroll
    for (int l = 0; l < 2; l++) {
        int idx = tid + l * 256;           // rows 0-127: 512 chunks
        int r = idx >> 2, c = (idx & 3) * 8;
        cp16(base + (r * A_ROWP + c) * 2, Gb + (size_t)r * NDIM + k0 + c);
    }
    if (tid < 4)                            // w row (row 128)
        cp16(base + (128 * A_ROWP + tid * 8) * 2, wb + k0 + tid * 8);
}

__global__ void __launch_bounds__(256, 1)
attn_mma_kernel(const float* __restrict__ A, float* __restrict__ out) {
    extern __shared__ __align__(16) char smem[];
    const uint32_t sb = smem_u32(smem);
    const int tid = threadIdx.x;
    const int lane = tid & 31;
    const int g = lane >> 2, t = lane & 3;
    const int wid = tid >> 5;
    const int wm = wid >> 2, wn = wid & 3;
    const int b = blockIdx.y, m0 = blockIdx.x * 128;

    const float* __restrict__ Ab = A + (size_t)b * NDIM * NDIM + (size_t)m0 * NDIM;
    const __half* __restrict__ Gb = g_gT + (size_t)b * CDIM * NDIM;
    const __half* __restrict__ wb = g_w + (size_t)b * NDIM;

    // zero B pad rows (129..135) of every stage — written once, never touched
#pragma unroll
    for (int s = 0; s < NSTAGE; s++)
        for (int i = tid; i < 7 * A_ROWP / 2; i += 256)
            *(uint32_t*)(smem + B_OFFB + s * B_STB + 129 * A_ROWP * 2 + i * 4) = 0u;

    float acc[4][4][4];
#pragma unroll
    for (int mf = 0; mf < 4; mf++)
#pragma unroll
        for (int ch = 0; ch < 4; ch++)
#pragma unroll
            for (int q = 0; q < 4; q++) acc[mf][ch][q] = 0.f;
    float dacc[4][4];
#pragma unroll
    for (int mf = 0; mf < 4; mf++)
#pragma unroll
        for (int q = 0; q < 4; q++) dacc[mf][q] = 0.f;

    // ldmatrix lane addresses (stage-relative)
    const uint32_t aLane = ((lane & 15) * A_ROWP + (lane >> 4) * 8) * 2;
    const uint32_t bLane = aLane;                                  // same pattern
    const int l16 = lane & 15;
    const uint32_t dLane = (((128 + (l16 & 7)) * A_ROWP) + (l16 >> 3) * 8) * 2;

    // prologue
    float4 ra[4];
    ldgA(Ab, 0, tid, ra);
    cpB(sb, 0, 0, tid, Gb, wb); CP_COMMIT();
    cpB(sb, 1, 1, tid, Gb, wb); CP_COMMIT();
    stsA(sb, 0, tid, ra);
    ldgA(Ab, 1, tid, ra);
    cpB(sb, 2, 2, tid, Gb, wb); CP_COMMIT();
    stsA(sb, 1, tid, ra);
    ldgA(Ab, 2, tid, ra);

    for (int it = 0; it < NITER; ++it) {
        const int s = it & (NSTAGE - 1);
        CP_WAIT(2);
        __syncthreads();

        if (it + 2 < NITER) stsA(sb, (it + 2) & (NSTAGE - 1), tid, ra);
        if (it + 3 < NITER) {
            ldgA(Ab, it + 3, tid, ra);
            cpB(sb, (it + 3) & (NSTAGE - 1), it + 3, tid, Gb, wb);
        }
        CP_COMMIT();

        const uint32_t aBase = sb + s * A_STB + (wm * 64 * A_ROWP) * 2 + aLane;
        const uint32_t bBase = sb + B_OFFB + s * B_STB + (wn * 32 * A_ROWP) * 2 + bLane;
        const uint32_t dBase = sb + B_OFFB + s * B_STB + dLane;
#pragma unroll
        for (int kk = 0; kk < 2; kk++) {
            const uint32_t kb = kk * 32;   // 16 halves
            uint32_t a0[4], a1[4], a2[4], a3[4];
#pragma unroll
            for (int mf = 0; mf < 4; mf++)
                LDSM_X4(a0[mf], a1[mf], a2[mf], a3[mf],
                        aBase + mf * 16 * A_ROWP * 2 + kb);
            uint32_t b0[4], b1[4];
#pragma unroll
            for (int nh = 0; nh < 2; nh++) {
                uint32_t r0, r1, r2, r3;
                LDSM_X4(r0, r1, r2, r3, bBase + nh * 16 * A_ROWP * 2 + kb);
                b0[nh * 2]     = r0; b1[nh * 2]     = r2;
                b0[nh * 2 + 1] = r1; b1[nh * 2 + 1] = r3;
            }
#pragma unroll
            for (int mf = 0; mf < 4; mf++)
#pragma unroll
                for (int ch = 0; ch < 4; ch++)
                    MMA_F16(acc[mf][ch], a0[mf], a1[mf], a2[mf], a3[mf],
                            b0[ch], b1[ch]);
            if (wn == 0) {
                uint32_t w0, w1;
                LDSM_X2(w0, w1, dBase + kb);
#pragma unroll
                for (int mf = 0; mf < 4; mf++)
                    MMA_F16(dacc[mf], a0[mf], a1[mf], a2[mf], a3[mf], w0, w1);
            }
        }
    }

    CP_WAIT(0);
    __syncthreads();

    // publish den (col n=0 of dacc lives at t==0: c0 -> row g, c2 -> row g+8)
    float* denS = (float*)(smem + DEN_OFFB);
    if (wn == 0 && t == 0) {
#pragma unroll
        for (int mf = 0; mf < 4; mf++) {
            denS[wm * 64 + mf * 16 + g]     = dacc[mf][0];
            denS[wm * 64 + mf * 16 + g + 8] = dacc[mf][2];
        }
    }
    __syncthreads();

    // scale + stage to smem stg[128][132]
    float* stg = (float*)smem;
#pragma unroll
    for (int mf = 0; mf < 4; mf++) {
        const int r0 = wm * 64 + mf * 16 + g;
        const int r1 = r0 + 8;
        const float inv0 = 1.0f / denS[r0];
        const float inv1 = 1.0f / denS[r1];
#pragma unroll
        for (int ch = 0; ch < 4; ch++) {
            const int col = wn * 32 + ch * 8 + 2 * t;
            *(float2*)&stg[r0 * 132 + col] =
                make_float2(acc[mf][ch][0] * inv0, acc[mf][ch][1] * inv0);
            *(float2*)&stg[r1 * 132 + col] =
                make_float2(acc[mf][ch][2] * inv1, acc[mf][ch][3] * inv1);
        }
    }
    __syncthreads();

    float* __restrict__ ob = out + ((size_t)b * NDIM + m0) * CDIM;
#pragma unroll
    for (int l = 0; l < 16; l++) {
        int idx = tid + l * 256;
        int r = idx >> 5, c = idx & 31;
        *(float4*)&ob[r * CDIM + c * 4] = *(const float4*)&stg[r * 132 + c * 4];
    }
}

// ---------------------------------------------------------------------------
extern "C" void kernel_launch(void* const* d_in, const int* in_sizes, int n_in,
                              void* d_out, int out_size) {
    (void)in_sizes; (void)n_in; (void)out_size;
    const float* h  = (const float*)d_in[0];
    const float* A  = (const float*)d_in[1];
    const float* Ww = (const float*)d_in[2];
    const float* Wb = (const float*)d_in[3];
    const float* aw = (const float*)d_in[4];
    float* out = (float*)d_out;

    cudaFuncSetAttribute(prep_g_kernel,
                         cudaFuncAttributeMaxDynamicSharedMemorySize, 128 * 129 * 4);
    cudaFuncSetAttribute(attn_mma_kernel,
                         cudaFuncAttributeMaxDynamicSharedMemorySize, SMEM_TOTAL);

    prep_g_kernel<<<dim3(NDIM / 128, BDIM), 256, 128 * 129 * 4>>>(h, Ww, Wb, aw);
    attn_mma_kernel<<<dim3(NDIM / 128, BDIM), 256, SMEM_TOTAL>>>(A, out);
}

// round 9
// speedup vs baseline: 6.8815x; 1.1595x over previous
#include <cuda_runtime.h>
#include <cuda_fp16.h>
#include <math.h>
#include <cstdint>

#define CDIM 128
#define BDIM 8
#define NDIM 2048

// ---------------- GEMM tiling (m64 x n128 CTA tile) ----------------
#define NSTAGE 4
#define BK 32
#define NITER (NDIM / BK)          // 64
#define A_ROWP 40                  // halves per row (32 data + 8 pad) -> 80B stride
#define A_STB (64 * A_ROWP * 2)    // 5120 B per A stage
#define B_STB (136 * A_ROWP * 2)   // 10880 B per B stage (128 g + 1 w + 7 zero)
#define B_OFFB (NSTAGE * A_STB)    // 20480
#define DEN_OFFB (B_OFFB + NSTAGE * B_STB)   // 64000
#define SMEM_TOTAL (DEN_OFFB + 64 * 4)       // 64256 B

// ---------------- device scratch ----------------
__device__ __half g_gT[BDIM * CDIM * NDIM];  // [b][c][j] = fp16(w*h)
__device__ __half g_w[BDIM * NDIM];          // [b][j]    = fp16(w)

// ---------------- helpers ----------------
__device__ __forceinline__ uint32_t smem_u32(const void* p) {
    uint32_t a;
    asm("{ .reg .u64 t; cvta.to.shared.u64 t, %1; cvt.u32.u64 %0, t; }" : "=r"(a) : "l"(p));
    return a;
}
__device__ __forceinline__ void cp16(uint32_t dst, const void* src) {
    asm volatile("cp.async.cg.shared.global [%0], [%1], 16;" :: "r"(dst), "l"(src));
}
#define CP_COMMIT() asm volatile("cp.async.commit_group;" ::: "memory")
#define CP_WAIT(n)  asm volatile("cp.async.wait_group %0;" :: "n"(n) : "memory")

#define LDSM_X4(r0, r1, r2, r3, a) \
    asm volatile("ldmatrix.sync.aligned.m8n8.x4.shared.b16 {%0,%1,%2,%3}, [%4];" \
        : "=r"(r0), "=r"(r1), "=r"(r2), "=r"(r3) : "r"(a))
#define LDSM_X2(r0, r1, a) \
    asm volatile("ldmatrix.sync.aligned.m8n8.x2.shared.b16 {%0,%1}, [%2];" \
        : "=r"(r0), "=r"(r1) : "r"(a))

#define MMA_F16(d, a0, a1, a2, a3, b0, b1) \
    asm volatile("mma.sync.aligned.m16n8k16.row.col.f32.f16.f16.f32 " \
        "{%0,%1,%2,%3}, {%4,%5,%6,%7}, {%8,%9}, {%0,%1,%2,%3};" \
        : "+f"((d)[0]), "+f"((d)[1]), "+f"((d)[2]), "+f"((d)[3]) \
        : "r"(a0), "r"(a1), "r"(a2), "r"(a3), "r"(b0), "r"(b1))

// ---------------------------------------------------------------------------
// prep_g: per 128-token tile (grid 16 x 8, 256 thr):
//   v[c] = sum_d Ww[d,c]*aw[C+d]  (8-way d-split, coalesced float4)
//   s0   = Wb . aw[C:]
//   w[j] = exp(h[j].v + s0)
//   g_gT[b][c][j] = fp16(w[j]*h[j][c]) ;  g_w[b][j] = fp16(w[j])
// ---------------------------------------------------------------------------
__global__ void __launch_bounds__(256)
prep_g_kernel(const float* __restrict__ h,
              const float* __restrict__ Ww,
              const float* __restrict__ Wb,
              const float* __restrict__ aw) {
    extern __shared__ float hs[];          // [128][129] (pad keeps reads conflict-free)
    __shared__ float vpart[8][128];
    __shared__ float awsh[CDIM];
    __shared__ float vsh[CDIM];
    __shared__ float wsh[128];
    __shared__ float s0sh;

    const int b  = blockIdx.y;
    const int j0 = blockIdx.x * 128;
    const int tid = threadIdx.x;
    const int wid = tid >> 5, lid = tid & 31;

    if (tid < CDIM) awsh[tid] = aw[CDIM + tid];
    __syncthreads();

    // v partials: thread (dp = tid>>5, c4 = (tid&31)*4), 16 coalesced float4 iters
    {
        const int dp = wid, c4 = lid * 4;
        float4 acc4 = make_float4(0.f, 0.f, 0.f, 0.f);
#pragma unroll
        for (int q = 0; q < 16; q++) {
            int d = dp + q * 8;
            float a2 = awsh[d];
            float4 wv = *(const float4*)&Ww[(size_t)d * CDIM + c4];
            acc4.x = fmaf(wv.x, a2, acc4.x);
            acc4.y = fmaf(wv.y, a2, acc4.y);
            acc4.z = fmaf(wv.z, a2, acc4.z);
            acc4.w = fmaf(wv.w, a2, acc4.w);
        }
        *(float4*)&vpart[dp][c4] = acc4;
    }

    // load h tile: float4 LDG, scalar STS (row stride 129*4B not 16B aligned)
    const float* hb = h + ((size_t)b * NDIM + j0) * CDIM;
#pragma unroll
    for (int l = 0; l < 16; l++) {
        int idx = tid + l * 256;           // float4 index, 4096 total
        int r = idx >> 5, c = (idx & 31) * 4;
        float4 v = *(const float4*)&hb[(size_t)r * CDIM + c];
        float* d = &hs[r * 129 + c];
        d[0] = v.x; d[1] = v.y; d[2] = v.z; d[3] = v.w;
    }
    __syncthreads();

    if (tid < CDIM) {
        float s = 0.f;
#pragma unroll
        for (int dp = 0; dp < 8; dp++) s += vpart[dp][tid];
        vsh[tid] = s;
    } else if (wid == 7) {
        float x = 0.f;
#pragma unroll
        for (int q = 0; q < 4; q++) {
            int d = lid + 32 * q;
            x += Wb[d] * awsh[d];
        }
#pragma unroll
        for (int o = 16; o > 0; o >>= 1) x += __shfl_down_sync(0xffffffffu, x, o);
        if (lid == 0) s0sh = x;
    }
    __syncthreads();

    // w per token (each warp: 16 tokens)
    const float s0 = s0sh;
#pragma unroll
    for (int rr = 0; rr < 16; rr++) {
        int r = wid * 16 + rr;
        float p = 0.f;
#pragma unroll
        for (int q = 0; q < 4; q++)
            p += hs[r * 129 + lid + 32 * q] * vsh[lid + 32 * q];
#pragma unroll
        for (int o = 16; o > 0; o >>= 1) p += __shfl_down_sync(0xffffffffu, p, o);
        if (lid == 0) wsh[r] = expf(p + s0);
    }
    __syncthreads();

    // write gT (fp16) coalesced in j
    __half* Gb = g_gT + (size_t)b * CDIM * NDIM;
#pragma unroll
    for (int l = 0; l < 64; l++) {
        int idx = tid + l * 256;           // 16384 total
        int c = idx >> 7, j = idx & 127;
        Gb[(size_t)c * NDIM + j0 + j] = __float2half_rn(wsh[j] * hs[j * 129 + c]);
    }
    if (tid < 128) g_w[(size_t)b * NDIM + j0 + tid] = __float2half_rn(wsh[tid]);
}

// ---------------------------------------------------------------------------
// Main GEMM (fp16 mma.sync): Num[64x128] = A_tile . G^T, Den via w-row MMA.
// 256 thr = 8 warps (wm 0-1 x wn 0-3), warp tile m32 x n32, 4-stage pipeline.
// Grid (32, 8) = 256 CTAs; 2 CTAs resident per SM.
// ---------------------------------------------------------------------------
__device__ __forceinline__ void ldgA(const float* __restrict__ Ab, int it, int tid,
                                     float4 (&ra)[2]) {
    const float* src = Ab + it * BK;
#pragma unroll
    for (int l = 0; l < 2; l++) {
        int idx = tid + l * 256;           // 512 float4 per stage
        int r = idx >> 3, c = (idx & 7) * 4;
        ra[l] = *(const float4*)&src[(size_t)r * NDIM + c];
    }
}
__device__ __forceinline__ void stsA(uint32_t sb, int s, int tid, const float4 (&ra)[2]) {
    const uint32_t base = sb + s * A_STB;
#pragma unroll
    for (int l = 0; l < 2; l++) {
        int idx = tid + l * 256;
        int r = idx >> 3, c = (idx & 7) * 4;
        __half2 h0 = __floats2half2_rn(ra[l].x, ra[l].y);
        __half2 h1 = __floats2half2_rn(ra[l].z, ra[l].w);
        asm volatile("st.shared.v2.b32 [%0], {%1,%2};"
                     :: "r"(base + (r * A_ROWP + c) * 2),
                        "r"(*(uint32_t*)&h0), "r"(*(uint32_t*)&h1) : "memory");
    }
}
__device__ __forceinline__ void cpB(uint32_t sb, int s, int it, int tid,
                                    const __half* __restrict__ Gb,
                                    const __half* __restrict__ wb) {
    const int k0 = it * BK;
    const uint32_t base = sb + B_OFFB + s * B_STB;
#pragma unroll
    for (int l = 0; l < 2; l++) {
        int idx = tid + l * 256;           // rows 0-127: 512 chunks
        int r = idx >> 2, c = (idx & 3) * 8;
        cp16(base + (r * A_ROWP + c) * 2, Gb + (size_t)r * NDIM + k0 + c);
    }
    if (tid < 4)                            // w row (row 128)
        cp16(base + (128 * A_ROWP + tid * 8) * 2, wb + k0 + tid * 8);
}

__global__ void __launch_bounds__(256, 2)
attn_mma_kernel(const float* __restrict__ A, float* __restrict__ out) {
    extern __shared__ __align__(16) char smem[];
    const uint32_t sb = smem_u32(smem);
    const int tid = threadIdx.x;
    const int lane = tid & 31;
    const int g = lane >> 2, t = lane & 3;
    const int wid = tid >> 5;
    const int wm = wid >> 2, wn = wid & 3;
    const int b = blockIdx.y, m0 = blockIdx.x * 64;

    const float* __restrict__ Ab = A + (size_t)b * NDIM * NDIM + (size_t)m0 * NDIM;
    const __half* __restrict__ Gb = g_gT + (size_t)b * CDIM * NDIM;
    const __half* __restrict__ wb = g_w + (size_t)b * NDIM;

    // zero B pad rows (129..135) of every stage
#pragma unroll
    for (int s = 0; s < NSTAGE; s++)
        for (int i = tid; i < 7 * A_ROWP / 2; i += 256)
            *(uint32_t*)(smem + B_OFFB + s * B_STB + 129 * A_ROWP * 2 + i * 4) = 0u;

    float acc[2][4][4];
#pragma unroll
    for (int mf = 0; mf < 2; mf++)
#pragma unroll
        for (int ch = 0; ch < 4; ch++)
#pragma unroll
            for (int q = 0; q < 4; q++) acc[mf][ch][q] = 0.f;
    float dacc[2][4];
#pragma unroll
    for (int mf = 0; mf < 2; mf++)
#pragma unroll
        for (int q = 0; q < 4; q++) dacc[mf][q] = 0.f;

    // ldmatrix lane addresses (stage-relative)
    const uint32_t aLane = ((lane & 15) * A_ROWP + (lane >> 4) * 8) * 2;
    const uint32_t bLane = aLane;
    const int l16 = lane & 15;
    const uint32_t dLane = (((128 + (l16 & 7)) * A_ROWP) + (l16 >> 3) * 8) * 2;

    // prologue
    float4 ra[2];
    ldgA(Ab, 0, tid, ra);
    cpB(sb, 0, 0, tid, Gb, wb); CP_COMMIT();
    cpB(sb, 1, 1, tid, Gb, wb); CP_COMMIT();
    stsA(sb, 0, tid, ra);
    ldgA(Ab, 1, tid, ra);
    cpB(sb, 2, 2, tid, Gb, wb); CP_COMMIT();
    stsA(sb, 1, tid, ra);
    ldgA(Ab, 2, tid, ra);

    for (int it = 0; it < NITER; ++it) {
        const int s = it & (NSTAGE - 1);
        CP_WAIT(2);
        __syncthreads();

        if (it + 2 < NITER) stsA(sb, (it + 2) & (NSTAGE - 1), tid, ra);
        if (it + 3 < NITER) {
            ldgA(Ab, it + 3, tid, ra);
            cpB(sb, (it + 3) & (NSTAGE - 1), it + 3, tid, Gb, wb);
        }
        CP_COMMIT();

        const uint32_t aBase = sb + s * A_STB + (wm * 32 * A_ROWP) * 2 + aLane;
        const uint32_t bBase = sb + B_OFFB + s * B_STB + (wn * 32 * A_ROWP) * 2 + bLane;
        const uint32_t dBase = sb + B_OFFB + s * B_STB + dLane;
#pragma unroll
        for (int kk = 0; kk < 2; kk++) {
            const uint32_t kb = kk * 32;   // 16 halves
            uint32_t a0[2], a1[2], a2[2], a3[2];
#pragma unroll
            for (int mf = 0; mf < 2; mf++)
                LDSM_X4(a0[mf], a1[mf], a2[mf], a3[mf],
                        aBase + mf * 16 * A_ROWP * 2 + kb);
            uint32_t b0[4], b1[4];
#pragma unroll
            for (int nh = 0; nh < 2; nh++) {
                uint32_t r0, r1, r2, r3;
                LDSM_X4(r0, r1, r2, r3, bBase + nh * 16 * A_ROWP * 2 + kb);
                b0[nh * 2]     = r0; b1[nh * 2]     = r2;
                b0[nh * 2 + 1] = r1; b1[nh * 2 + 1] = r3;
            }
#pragma unroll
            for (int mf = 0; mf < 2; mf++)
#pragma unroll
                for (int ch = 0; ch < 4; ch++)
                    MMA_F16(acc[mf][ch], a0[mf], a1[mf], a2[mf], a3[mf],
                            b0[ch], b1[ch]);
            if (wn == 0) {
                uint32_t w0, w1;
                LDSM_X2(w0, w1, dBase + kb);
#pragma unroll
                for (int mf = 0; mf < 2; mf++)
                    MMA_F16(dacc[mf], a0[mf], a1[mf], a2[mf], a3[mf], w0, w1);
            }
        }
    }

    CP_WAIT(0);
    __syncthreads();

    // publish den (n=0 column of dacc: c0 -> row g, c2 -> row g+8, at t==0)
    float* denS = (float*)(smem + DEN_OFFB);
    if (wn == 0 && t == 0) {
#pragma unroll
        for (int mf = 0; mf < 2; mf++) {
            denS[wm * 32 + mf * 16 + g]     = dacc[mf][0];
            denS[wm * 32 + mf * 16 + g + 8] = dacc[mf][2];
        }
    }
    __syncthreads();

    // scale + stage to smem stg[64][132]
    float* stg = (float*)smem;
#pragma unroll
    for (int mf = 0; mf < 2; mf++) {
        const int r0 = wm * 32 + mf * 16 + g;
        const int r1 = r0 + 8;
        const float inv0 = 1.0f / denS[r0];
        const float inv1 = 1.0f / denS[r1];
#pragma unroll
        for (int ch = 0; ch < 4; ch++) {
            const int col = wn * 32 + ch * 8 + 2 * t;
            *(float2*)&stg[r0 * 132 + col] =
                make_float2(acc[mf][ch][0] * inv0, acc[mf][ch][1] * inv0);
            *(float2*)&stg[r1 * 132 + col] =
                make_float2(acc[mf][ch][2] * inv1, acc[mf][ch][3] * inv1);
        }
    }
    __syncthreads();

    float* __restrict__ ob = out + ((size_t)b * NDIM + m0) * CDIM;
#pragma unroll
    for (int l = 0; l < 8; l++) {
        int idx = tid + l * 256;           // 2048 float4
        int r = idx >> 5, c = idx & 31;
        *(float4*)&ob[r * CDIM + c * 4] = *(const float4*)&stg[r * 132 + c * 4];
    }
}

// ---------------------------------------------------------------------------
extern "C" void kernel_launch(void* const* d_in, const int* in_sizes, int n_in,
                              void* d_out, int out_size) {
    (void)in_sizes; (void)n_in; (void)out_size;
    const float* h  = (const float*)d_in[0];
    const float* A  = (const float*)d_in[1];
    const float* Ww = (const float*)d_in[2];
    const float* Wb = (const float*)d_in[3];
    const float* aw = (const float*)d_in[4];
    float* out = (float*)d_out;

    cudaFuncSetAttribute(prep_g_kernel,
                         cudaFuncAttributeMaxDynamicSharedMemorySize, 128 * 129 * 4);
    cudaFuncSetAttribute(attn_mma_kernel,
                         cudaFuncAttributeMaxDynamicSharedMemorySize, SMEM_TOTAL);

    prep_g_kernel<<<dim3(NDIM / 128, BDIM), 256, 128 * 129 * 4>>>(h, Ww, Wb, aw);
    attn_mma_kernel<<<dim3(NDIM / 64, BDIM), 256, SMEM_TOTAL>>>(A, out);
}

// round 11
// speedup vs baseline: 8.4280x; 1.2247x over previous
#include <cuda_runtime.h>
#include <cuda_fp16.h>
#include <math.h>
#include <cstdint>

#define CDIM 128
#define BDIM 8
#define NDIM 2048

// ---------------- GEMM tiling (m64 x n128 CTA tile, BK=64, double buffer) ----
#define NSTAGE 2
#define BK 64
#define NITER (NDIM / BK)          // 32
#define A_ROWP 72                  // halves per row (64 data + 8 pad) -> 144B stride
#define A_STB (64 * A_ROWP * 2)    // 9216 B per A stage
#define B_STB (136 * A_ROWP * 2)   // 19584 B per B stage (128 g + 1 w + 7 zero)
#define B_OFFB (NSTAGE * A_STB)    // 18432
#define DEN_OFFB (B_OFFB + NSTAGE * B_STB)   // 57600
#define SMEM_TOTAL (DEN_OFFB + 64 * 4)       // 57856 B

// ---------------- device scratch ----------------
__device__ __half g_gT[BDIM * CDIM * NDIM];  // [b][c][j] = fp16(w*h)
__device__ __half g_w[BDIM * NDIM];          // [b][j]    = fp16(w)

// ---------------- helpers ----------------
__device__ __forceinline__ uint32_t smem_u32(const void* p) {
    uint32_t a;
    asm("{ .reg .u64 t; cvta.to.shared.u64 t, %1; cvt.u32.u64 %0, t; }" : "=r"(a) : "l"(p));
    return a;
}
__device__ __forceinline__ void cp16(uint32_t dst, const void* src) {
    asm volatile("cp.async.cg.shared.global [%0], [%1], 16;" :: "r"(dst), "l"(src));
}
#define CP_COMMIT() asm volatile("cp.async.commit_group;" ::: "memory")
#define CP_WAIT0()  asm volatile("cp.async.wait_group 0;" ::: "memory")

#define LDSM_X4(r0, r1, r2, r3, a) \
    asm volatile("ldmatrix.sync.aligned.m8n8.x4.shared.b16 {%0,%1,%2,%3}, [%4];" \
        : "=r"(r0), "=r"(r1), "=r"(r2), "=r"(r3) : "r"(a))
#define LDSM_X2(r0, r1, a) \
    asm volatile("ldmatrix.sync.aligned.m8n8.x2.shared.b16 {%0,%1}, [%2];" \
        : "=r"(r0), "=r"(r1) : "r"(a))

#define MMA_F16(d, a0, a1, a2, a3, b0, b1) \
    asm volatile("mma.sync.aligned.m16n8k16.row.col.f32.f16.f16.f32 " \
        "{%0,%1,%2,%3}, {%4,%5,%6,%7}, {%8,%9}, {%0,%1,%2,%3};" \
        : "+f"((d)[0]), "+f"((d)[1]), "+f"((d)[2]), "+f"((d)[3]) \
        : "r"(a0), "r"(a1), "r"(a2), "r"(a3), "r"(b0), "r"(b1))

// ---------------------------------------------------------------------------
// prep_g: per 64-token tile (grid 32 x 8, 256 thr):
//   v[c] = sum_d Ww[d,c]*aw[C+d]  (8-way d-split, coalesced float4)
//   s0   = Wb . aw[C:]
//   w[j] = exp(h[j].v + s0)      (4 threads per token, smem partials)
//   g_gT[b][c][j] = fp16(w[j]*h[j][c]) ;  g_w[b][j] = fp16(w[j])
// ---------------------------------------------------------------------------
#define PTOK 64
__global__ void __launch_bounds__(256)
prep_g_kernel(const float* __restrict__ h,
              const float* __restrict__ Ww,
              const float* __restrict__ Wb,
              const float* __restrict__ aw) {
    extern __shared__ float hs[];          // [64][129]
    __shared__ float vpart[8][128];
    __shared__ float spart[4][PTOK];
    __shared__ float awsh[CDIM];
    __shared__ float vsh[CDIM];
    __shared__ float wsh[PTOK];
    __shared__ float s0sh;

    const int b  = blockIdx.y;
    const int j0 = blockIdx.x * PTOK;
    const int tid = threadIdx.x;
    const int wid = tid >> 5, lid = tid & 31;

    if (tid < CDIM) awsh[tid] = aw[CDIM + tid];
    __syncthreads();

    // v partials
    {
        const int dp = wid, c4 = lid * 4;
        float4 acc4 = make_float4(0.f, 0.f, 0.f, 0.f);
#pragma unroll
        for (int q = 0; q < 16; q++) {
            int d = dp + q * 8;
            float a2 = awsh[d];
            float4 wv = *(const float4*)&Ww[(size_t)d * CDIM + c4];
            acc4.x = fmaf(wv.x, a2, acc4.x);
            acc4.y = fmaf(wv.y, a2, acc4.y);
            acc4.z = fmaf(wv.z, a2, acc4.z);
            acc4.w = fmaf(wv.w, a2, acc4.w);
        }
        *(float4*)&vpart[dp][c4] = acc4;
    }

    // load h tile (scalar STS: 129-row stride not 16B aligned)
    const float* hb = h + ((size_t)b * NDIM + j0) * CDIM;
#pragma unroll
    for (int l = 0; l < 8; l++) {
        int idx = tid + l * 256;           // 2048 float4
        int r = idx >> 5, c = (idx & 31) * 4;
        float4 v = *(const float4*)&hb[(size_t)r * CDIM + c];
        float* d = &hs[r * 129 + c];
        d[0] = v.x; d[1] = v.y; d[2] = v.z; d[3] = v.w;
    }
    __syncthreads();

    if (tid < CDIM) {
        float s = 0.f;
#pragma unroll
        for (int dp = 0; dp < 8; dp++) s += vpart[dp][tid];
        vsh[tid] = s;
    } else if (wid == 7) {
        float x = 0.f;
#pragma unroll
        for (int q = 0; q < 4; q++) {
            int d = lid + 32 * q;
            x += Wb[d] * awsh[d];
        }
#pragma unroll
        for (int o = 16; o > 0; o >>= 1) x += __shfl_down_sync(0xffffffffu, x, o);
        if (lid == 0) s0sh = x;
    }
    __syncthreads();

    // sj partials: thread (part = tid>>6, j = tid&63) sums 32 channels
    {
        const int part = tid >> 6, j = tid & 63;
        const int c0 = part * 32;
        float p = 0.f;
#pragma unroll
        for (int q = 0; q < 32; q++)
            p = fmaf(hs[j * 129 + c0 + q], vsh[c0 + q], p);
        spart[part][j] = p;
    }
    __syncthreads();
    if (tid < PTOK)
        wsh[tid] = expf(spart[0][tid] + spart[1][tid] + spart[2][tid] +
                        spart[3][tid] + s0sh);
    __syncthreads();

    // write gT (fp16), coalesced in j (64 halves = 128B per row-chunk)
    __half* Gb = g_gT + (size_t)b * CDIM * NDIM;
#pragma unroll
    for (int l = 0; l < 32; l++) {
        int idx = tid + l * 256;           // 8192 total
        int c = idx >> 6, j = idx & 63;
        Gb[(size_t)c * NDIM + j0 + j] = __float2half_rn(wsh[j] * hs[j * 129 + c]);
    }
    if (tid < PTOK) g_w[(size_t)b * NDIM + j0 + tid] = __float2half_rn(wsh[tid]);
}

// ---------------------------------------------------------------------------
// Main GEMM (fp16 mma.sync): Num[64x128] = A_tile . G^T, Den via w-row MMA.
// 256 thr = 8 warps (wm 0-1 x wn 0-3), warp tile m32 x n32.
// BK=64, double-buffered (1 cp.async group in flight), 32 iterations.
// ---------------------------------------------------------------------------
__device__ __forceinline__ void ldgA(const float* __restrict__ Ab, int it, int tid,
                                     float4 (&ra)[4]) {
    const float* src = Ab + it * BK;
#pragma unroll
    for (int l = 0; l < 4; l++) {
        int idx = tid + l * 256;           // 1024 float4 per stage
        int r = idx >> 4, c = (idx & 15) * 4;
        ra[l] = *(const float4*)&src[(size_t)r * NDIM + c];
    }
}
__device__ __forceinline__ void stsA(uint32_t sb, int s, int tid, const float4 (&ra)[4]) {
    const uint32_t base = sb + s * A_STB;
#pragma unroll
    for (int l = 0; l < 4; l++) {
        int idx = tid + l * 256;
        int r = idx >> 4, c = (idx & 15) * 4;
        __half2 h0 = __floats2half2_rn(ra[l].x, ra[l].y);
        __half2 h1 = __floats2half2_rn(ra[l].z, ra[l].w);
        asm volatile("st.shared.v2.b32 [%0], {%1,%2};"
                     :: "r"(base + (r * A_ROWP + c) * 2),
                        "r"(*(uint32_t*)&h0), "r"(*(uint32_t*)&h1) : "memory");
    }
}
__device__ __forceinline__ void cpB(uint32_t sb, int s, int it, int tid,
                                    const __half* __restrict__ Gb,
                                    const __half* __restrict__ wb) {
    const int k0 = it * BK;
    const uint32_t base = sb + B_OFFB + s * B_STB;
#pragma unroll
    for (int l = 0; l < 4; l++) {
        int idx = tid + l * 256;           // rows 0-127: 1024 chunks
        int r = idx >> 3, c = (idx & 7) * 8;
        cp16(base + (r * A_ROWP + c) * 2, Gb + (size_t)r * NDIM + k0 + c);
    }
    if (tid < 8)                            // w row (row 128): 8 chunks
        cp16(base + (128 * A_ROWP + tid * 8) * 2, wb + k0 + tid * 8);
}

__global__ void __launch_bounds__(256, 2)
attn_mma_kernel(const float* __restrict__ A, float* __restrict__ out) {
    extern __shared__ __align__(16) char smem[];
    const uint32_t sb = smem_u32(smem);
    const int tid = threadIdx.x;
    const int lane = tid & 31;
    const int g = lane >> 2, t = lane & 3;
    const int wid = tid >> 5;
    const int wm = wid >> 2, wn = wid & 3;
    const int b = blockIdx.y, m0 = blockIdx.x * 64;

    const float* __restrict__ Ab = A + (size_t)b * NDIM * NDIM + (size_t)m0 * NDIM;
    const __half* __restrict__ Gb = g_gT + (size_t)b * CDIM * NDIM;
    const __half* __restrict__ wb = g_w + (size_t)b * NDIM;

    // zero B pad rows (129..135) of both stages
#pragma unroll
    for (int s = 0; s < NSTAGE; s++)
        for (int i = tid; i < 7 * A_ROWP / 2; i += 256)
            *(uint32_t*)(smem + B_OFFB + s * B_STB + 129 * A_ROWP * 2 + i * 4) = 0u;

    float acc[2][4][4];
#pragma unroll
    for (int mf = 0; mf < 2; mf++)
#pragma unroll
        for (int ch = 0; ch < 4; ch++)
#pragma unroll
            for (int q = 0; q < 4; q++) acc[mf][ch][q] = 0.f;
    float dacc[2][4];
#pragma unroll
    for (int mf = 0; mf < 2; mf++)
#pragma unroll
        for (int q = 0; q < 4; q++) dacc[mf][q] = 0.f;

    // ldmatrix lane addresses (stage-relative, bytes)
    const uint32_t aLane = ((lane & 15) * A_ROWP + (lane >> 4) * 8) * 2;
    const uint32_t bLane = aLane;
    const int l16 = lane & 15;
    const uint32_t dLane = (((128 + (l16 & 7)) * A_ROWP) + (l16 >> 3) * 8) * 2;

    // prologue
    float4 ra[4];
    ldgA(Ab, 0, tid, ra);
    stsA(sb, 0, tid, ra);
    cpB(sb, 0, 0, tid, Gb, wb); CP_COMMIT();
    ldgA(Ab, 1, tid, ra);

    for (int it = 0; it < NITER; ++it) {
        const int s = it & 1;
        CP_WAIT0();                 // stage s B resident
        __syncthreads();            // everyone done with stage 1-s

        if (it + 1 < NITER) {
            stsA(sb, 1 - s, tid, ra);                 // A for it+1
            cpB(sb, 1 - s, it + 1, tid, Gb, wb);      // B for it+1
        }
        CP_COMMIT();
        if (it + 2 < NITER) ldgA(Ab, it + 2, tid, ra);

        const uint32_t aBase = sb + s * A_STB + (wm * 32 * A_ROWP) * 2 + aLane;
        const uint32_t bBase = sb + B_OFFB + s * B_STB + (wn * 32 * A_ROWP) * 2 + bLane;
        const uint32_t dBase = sb + B_OFFB + s * B_STB + dLane;
#pragma unroll
        for (int kk = 0; kk < 4; kk++) {
            const uint32_t kb = kk * 32;   // 16 halves = 32 B
            uint32_t a0[2], a1[2], a2[2], a3[2];
#pragma unroll
            for (int mf = 0; mf < 2; mf++)
                LDSM_X4(a0[mf], a1[mf], a2[mf], a3[mf],
                        aBase + mf * 16 * A_ROWP * 2 + kb);
            uint32_t b0[4], b1[4];
#pragma unroll
            for (int nh = 0; nh < 2; nh++) {
                uint32_t r0, r1, r2, r3;
                LDSM_X4(r0, r1, r2, r3, bBase + nh * 16 * A_ROWP * 2 + kb);
                b0[nh * 2]     = r0; b1[nh * 2]     = r2;
                b0[nh * 2 + 1] = r1; b1[nh * 2 + 1] = r3;
            }
#pragma unroll
            for (int mf = 0; mf < 2; mf++)
#pragma unroll
                for (int ch = 0; ch < 4; ch++)
                    MMA_F16(acc[mf][ch], a0[mf], a1[mf], a2[mf], a3[mf],
                            b0[ch], b1[ch]);
            if (wn == 0) {
                uint32_t w0, w1;
                LDSM_X2(w0, w1, dBase + kb);
#pragma unroll
                for (int mf = 0; mf < 2; mf++)
                    MMA_F16(dacc[mf], a0[mf], a1[mf], a2[mf], a3[mf], w0, w1);
            }
        }
    }

    __syncthreads();

    // publish den (n=0 column of dacc: c0 -> row g, c2 -> row g+8, at t==0)
    float* denS = (float*)(smem + DEN_OFFB);
    if (wn == 0 && t == 0) {
#pragma unroll
        for (int mf = 0; mf < 2; mf++) {
            denS[wm * 32 + mf * 16 + g]     = dacc[mf][0];
            denS[wm * 32 + mf * 16 + g + 8] = dacc[mf][2];
        }
    }
    __syncthreads();

    // scale + stage to smem stg[64][132]
    float* stg = (float*)smem;
#pragma unroll
    for (int mf = 0; mf < 2; mf++) {
        const int r0 = wm * 32 + mf * 16 + g;
        const int r1 = r0 + 8;
        const float inv0 = 1.0f / denS[r0];
        const float inv1 = 1.0f / denS[r1];
#pragma unroll
        for (int ch = 0; ch < 4; ch++) {
            const int col = wn * 32 + ch * 8 + 2 * t;
            *(float2*)&stg[r0 * 132 + col] =
                make_float2(acc[mf][ch][0] * inv0, acc[mf][ch][1] * inv0);
            *(float2*)&stg[r1 * 132 + col] =
                make_float2(acc[mf][ch][2] * inv1, acc[mf][ch][3] * inv1);
        }
    }
    __syncthreads();

    float* __restrict__ ob = out + ((size_t)b * NDIM + m0) * CDIM;
#pragma unroll
    for (int l = 0; l < 8; l++) {
        int idx = tid + l * 256;           // 2048 float4
        int r = idx >> 5, c = idx & 31;
        *(float4*)&ob[r * CDIM + c * 4] = *(const float4*)&stg[r * 132 + c * 4];
    }
}

// ---------------------------------------------------------------------------
extern "C" void kernel_launch(void* const* d_in, const int* in_sizes, int n_in,
                              void* d_out, int out_size) {
    (void)in_sizes; (void)n_in; (void)out_size;
    const float* h  = (const float*)d_in[0];
    const float* A  = (const float*)d_in[1];
    const float* Ww = (const float*)d_in[2];
    const float* Wb = (const float*)d_in[3];
    const float* aw = (const float*)d_in[4];
    float* out = (float*)d_out;

    cudaFuncSetAttribute(prep_g_kernel,
                         cudaFuncAttributeMaxDynamicSharedMemorySize, PTOK * 129 * 4);
    cudaFuncSetAttribute(attn_mma_kernel,
                         cudaFuncAttributeMaxDynamicSharedMemorySize, SMEM_TOTAL);

    prep_g_kernel<<<dim3(NDIM / PTOK, BDIM), 256, PTOK * 129 * 4>>>(h, Ww, Wb, aw);
    attn_mma_kernel<<<dim3(NDIM / 64, BDIM), 256, SMEM_TOTAL>>>(A, out);
}